// round 10
// baseline (speedup 1.0000x reference)
#include <cuda_runtime.h>
#include <cuda_fp16.h>
#include <math.h>

#define H  1024
#define H3 3072
#define B  64
#define T  256
#define LOSC   2048.0f
#define ILOSC  (1.0f/2048.0f)
#define NBLK   128

// ---------------- scratch (static __device__: no runtime allocation) -------
static __device__ float g_GI0[(size_t)T * B * H3];
static __device__ float g_GXF[T * B];
static __device__ float g_u[H];
static __device__ float g_v[H];
static __device__ float g_c;
static __device__ float g_h0s[B * H];
static __device__ float g_h1s[B * H];
static __device__ float g_h0n[B * H];
static __device__ float g_GA[B * H3];
static __device__ float g_GB[B * H3];

static __device__ uint4 g_xp[(size_t)B * T * 256];
static __device__ uint4 g_pW[4][(size_t)H3 * 256];
static __device__ uint4 g_h0p [B * 256];
static __device__ uint4 g_h1p [B * 256];
static __device__ uint4 g_h0np[B * 256];

static __device__ unsigned g_barCnt;
static __device__ unsigned g_barGen;

__device__ __forceinline__ float sigf(float x) { return 1.0f / (1.0f + expf(-x)); }

__device__ __forceinline__ unsigned pk2(float a, float b) {
    __half2 h = __floats2half2_rn(a, b);
    return *reinterpret_cast<unsigned*>(&h);
}
__device__ __forceinline__ float rlo(float x) {
    return (x - __half2float(__float2half_rn(x))) * LOSC;
}
__device__ __forceinline__ uint4 pack4(float v0, float v1, float v8, float v9) {
    uint4 p;
    p.x = pk2(v0, v1);           p.y = pk2(v8, v9);
    p.z = pk2(rlo(v0), rlo(v1)); p.w = pk2(rlo(v8), rlo(v9));
    return p;
}

__device__ __forceinline__ void mma_f16(float* c, unsigned a0, unsigned a1,
                                        unsigned a2, unsigned a3,
                                        unsigned b0, unsigned b1) {
    asm volatile(
        "mma.sync.aligned.m16n8k16.row.col.f32.f16.f16.f32 "
        "{%0,%1,%2,%3}, {%4,%5,%6,%7}, {%8,%9}, {%0,%1,%2,%3};\n"
        : "+f"(c[0]), "+f"(c[1]), "+f"(c[2]), "+f"(c[3])
        : "r"(a0), "r"(a1), "r"(a2), "r"(a3), "r"(b0), "r"(b1));
}
__device__ __forceinline__ void mma3s(float* ch, float* cl, const uint4& al,
                                      const uint4& ah, const uint4& wv) {
    mma_f16(ch, al.x, ah.x, al.y, ah.y, wv.x, wv.y);
    mma_f16(cl, al.x, ah.x, al.y, ah.y, wv.z, wv.w);
    mma_f16(cl, al.z, ah.z, al.w, ah.w, wv.x, wv.y);
}

// ---------------- grid barrier (all NBLK blocks co-resident) ----------------
__device__ __forceinline__ void gbar(unsigned& gen) {
    __syncthreads();
    if (threadIdx.x == 0) {
        __threadfence();
        if (atomicAdd(&g_barCnt, 1u) == (unsigned)(NBLK - 1)) {
            g_barCnt = 0u;
            __threadfence();
            atomicExch(&g_barGen, gen + 1u);
        } else {
            while (*((volatile unsigned*)&g_barGen) < gen + 1u) __nanosleep(64);
        }
    }
    __syncthreads();
    ++gen;
}

// ---------------- init ------------------------------------------------------
__global__ void init_kernel(const float* __restrict__ h0)
{
    int b = blockIdx.x;
    int ks = threadIdx.x >> 2, tc = threadIdx.x & 3;
    int j = ks * 16 + 2 * tc;
    float2 a = *(const float2*)(h0 + j);
    float2 c = *(const float2*)(h0 + j + 8);
    *(float2*)(g_h0s + b * H + j)     = a;
    *(float2*)(g_h0s + b * H + j + 8) = c;
    *(float2*)(g_h1s + b * H + j)     = a;
    *(float2*)(g_h1s + b * H + j + 8) = c;
    uint4 p = pack4(a.x, a.y, c.x, c.y);
    g_h0p[(b * 64 + ks) * 4 + tc] = p;
    g_h1p[(b * 64 + ks) * 4 + tc] = p;
    if (b == 0 && threadIdx.x == 0) { g_barCnt = 0u; g_barGen = 0u; }
}

// ---------------- gate folding ---------------------------------------------
__global__ void uvc_kernel(const float* __restrict__ gW1, const float* __restrict__ gW2,
                           const float* __restrict__ gWF, const float* __restrict__ gb1,
                           const float* __restrict__ gb2, const float* __restrict__ gbF)
{
    int bid = blockIdx.x;
    if (bid < 32) {
        int mat = bid >> 4, kc = bid & 15;
        const float* W = mat ? gW2 : gW1;
        float* dst = mat ? g_v : g_u;
        int k = kc * 64 + threadIdx.x;
        float s = 0.0f;
        for (int j = 0; j < H; ++j) s += gWF[j] * W[(size_t)j * H + k];
        dst[k] = s;
    } else {
        __shared__ float red[64];
        float s = 0.0f;
        for (int j = threadIdx.x; j < H; j += 64) s += gWF[j] * (gb1[j] + gb2[j]);
        red[threadIdx.x] = s;
        __syncthreads();
        for (int off = 32; off > 0; off >>= 1) {
            if (threadIdx.x < off) red[threadIdx.x] += red[threadIdx.x + off];
            __syncthreads();
        }
        if (threadIdx.x == 0) g_c = red[0] + gbF[0];
    }
}

// ---------------- gate input precompute ------------------------------------
__global__ void gxf_kernel(const float* __restrict__ x)
{
    int t = blockIdx.x, b = blockIdx.y;
    int tn = (t + 1 < T) ? (t + 1) : (T - 1);
    const float* xr = x + ((size_t)b * T + tn) * H;
    float s = 0.0f;
    for (int k = threadIdx.x; k < H; k += blockDim.x) s += xr[k] * g_u[k];
    __shared__ float red[128];
    red[threadIdx.x] = s;
    __syncthreads();
    for (int off = 64; off > 0; off >>= 1) {
        if (threadIdx.x < off) red[threadIdx.x] += red[threadIdx.x + off];
        __syncthreads();
    }
    if (threadIdx.x == 0) g_GXF[t * B + b] = red[0] + g_c;
}

// ---------------- pack weights ---------------------------------------------
__global__ void packw_kernel(const float* __restrict__ W_ih, const float* __restrict__ W_hh)
{
    int row = blockIdx.x, mat = blockIdx.y;
    int ks = threadIdx.x >> 2, tc = threadIdx.x & 3;
    const float* src = (mat == 0) ? W_ih : (mat == 1) ? W_hh
                     : (mat == 2) ? (W_ih + (size_t)H3 * H) : (W_hh + (size_t)H3 * H);
    int k0 = ks * 16 + 2 * tc;
    const float* r = src + (size_t)row * H;
    float2 a = *(const float2*)(r + k0);
    float2 c = *(const float2*)(r + k0 + 8);
    g_pW[mat][((size_t)row * 64 + ks) * 4 + tc] = pack4(a.x, a.y, c.x, c.y);
}

// ---------------- pack x ----------------------------------------------------
__global__ void packx_kernel(const float* __restrict__ x)
{
    int t = blockIdx.x, b = blockIdx.y;
    int ks = threadIdx.x >> 2, tc = threadIdx.x & 3;
    int k0 = ks * 16 + 2 * tc;
    const float* r = x + ((size_t)b * T + t) * H;
    float2 a = *(const float2*)(r + k0);
    float2 c = *(const float2*)(r + k0 + 8);
    g_xp[((size_t)(b * T + t) * 64 + ks) * 4 + tc] = pack4(a.x, a.y, c.x, c.y);
}

// ---------------- gi0: GI0[t] = x_t @ Wih0^T + bih0 (mma.sync) --------------
__global__ void gi0_kernel(const float* __restrict__ bih0)
{
    int tid = threadIdx.x, w = tid >> 5, lane = tid & 31;
    int mt = w & 3, jh = w >> 2;
    int g = lane >> 2, tc = lane & 3;
    int j0 = blockIdx.x * 16, t = blockIdx.y;
    int b0 = mt * 16 + g;
    int jrow = j0 + jh * 8 + g;

    float h0a[4] = {0,0,0,0}, l0a[4] = {0,0,0,0};
    float h1a[4] = {0,0,0,0}, l1a[4] = {0,0,0,0};
    float h2a[4] = {0,0,0,0}, l2a[4] = {0,0,0,0};
    const uint4* Ap0 = g_xp + ((size_t)b0 * T + t) * 256 + tc;
    const uint4* Ap1 = Ap0 + (size_t)8 * T * 256;
    const uint4* B0 = g_pW[0] + (size_t)jrow * 256 + tc;
    const uint4* B1 = g_pW[0] + (size_t)(H + jrow) * 256 + tc;
    const uint4* B2 = g_pW[0] + (size_t)(2 * H + jrow) * 256 + tc;

    #pragma unroll 4
    for (int ks = 0; ks < 64; ++ks) {
        uint4 al = Ap0[ks * 4], ah = Ap1[ks * 4];
        uint4 w0 = B0[ks * 4], w1 = B1[ks * 4], w2 = B2[ks * 4];
        mma3s(h0a, l0a, al, ah, w0);
        mma3s(h1a, l1a, al, ah, w1);
        mma3s(h2a, l2a, al, ah, w2);
    }
    int jA = j0 + jh * 8 + 2 * tc;
    float2 br = *(const float2*)(bih0 + jA);
    float2 bz = *(const float2*)(bih0 + H + jA);
    float2 bn = *(const float2*)(bih0 + 2 * H + jA);
    #pragma unroll
    for (int rs = 0; rs < 2; ++rs) {
        int row = b0 + 8 * rs;
        float* dst = g_GI0 + ((size_t)t * B + row) * H3;
        float2 o;
        o.x = h0a[2*rs] + l0a[2*rs]*ILOSC + br.x;
        o.y = h0a[2*rs+1] + l0a[2*rs+1]*ILOSC + br.y; *(float2*)(dst + jA) = o;
        o.x = h1a[2*rs] + l1a[2*rs]*ILOSC + bz.x;
        o.y = h1a[2*rs+1] + l1a[2*rs+1]*ILOSC + bz.y; *(float2*)(dst + H + jA) = o;
        o.x = h2a[2*rs] + l2a[2*rs]*ILOSC + bn.x;
        o.y = h2a[2*rs+1] + l2a[2*rs+1]*ILOSC + bn.y; *(float2*)(dst + 2*H + jA) = o;
    }
}

// ---------------- phase bodies ----------------------------------------------
// Loop-carried cross-block buffers read with __ldcg (L2 coherence point).

__device__ __forceinline__ void l0_body(int t, int j0, const float* __restrict__ bhh0,
                                        float (*s_hn)[17])
{
    int tid = threadIdx.x, w = tid >> 5, lane = tid & 31;
    int mt = w & 3, jh = w >> 2;
    int g = lane >> 2, tc = lane & 3;
    int b0 = mt * 16 + g;
    int jrow = j0 + jh * 8 + g;
    int jA = j0 + jh * 8 + 2 * tc;

    // prefetch epilogue operands (GI0 streams from DRAM: issue loads early
    // so their latency overlaps the mma loop instead of the phase tail)
    float2 pgr[2], pgz[2], pgn[2], php[2];
    #pragma unroll
    for (int rs = 0; rs < 2; ++rs) {
        int row = b0 + 8 * rs;
        const float* gi = g_GI0 + ((size_t)t * B + row) * H3;
        pgr[rs] = *(const float2*)(gi + jA);
        pgz[rs] = *(const float2*)(gi + H + jA);
        pgn[rs] = *(const float2*)(gi + 2 * H + jA);
        php[rs] = __ldcg((const float2*)(g_h0s + row * H + jA));
    }

    float h0a[4] = {0,0,0,0}, l0a[4] = {0,0,0,0};
    float h1a[4] = {0,0,0,0}, l1a[4] = {0,0,0,0};
    float h2a[4] = {0,0,0,0}, l2a[4] = {0,0,0,0};
    const uint4* Ap0 = g_h0p + (size_t)b0 * 256 + tc;
    const uint4* Ap1 = Ap0 + 8 * 256;
    const uint4* B0 = g_pW[1] + (size_t)jrow * 256 + tc;
    const uint4* B1 = g_pW[1] + (size_t)(H + jrow) * 256 + tc;
    const uint4* B2 = g_pW[1] + (size_t)(2 * H + jrow) * 256 + tc;

    #pragma unroll 8
    for (int ks = 0; ks < 64; ++ks) {
        uint4 al = __ldcg(Ap0 + ks * 4), ah = __ldcg(Ap1 + ks * 4);
        uint4 w0 = B0[ks * 4], w1 = B1[ks * 4], w2 = B2[ks * 4];
        mma3s(h0a, l0a, al, ah, w0);
        mma3s(h1a, l1a, al, ah, w1);
        mma3s(h2a, l2a, al, ah, w2);
    }
    float2 bhr = *(const float2*)(bhh0 + jA);
    float2 bhz = *(const float2*)(bhh0 + H + jA);
    float2 bhn = *(const float2*)(bhh0 + 2 * H + jA);
    #pragma unroll
    for (int rs = 0; rs < 2; ++rs) {
        int row = b0 + 8 * rs;
        float2 gr = pgr[rs], gz = pgz[rs], gn = pgn[rs], hp = php[rs];
        float2 o;
        {
            float ar = h0a[2*rs] + l0a[2*rs]*ILOSC;
            float az = h1a[2*rs] + l1a[2*rs]*ILOSC;
            float an = h2a[2*rs] + l2a[2*rs]*ILOSC;
            float r = sigf(gr.x + ar + bhr.x);
            float z = sigf(gz.x + az + bhz.x);
            float n = tanhf(gn.x + r * (an + bhn.x));
            o.x = (1.0f - z) * n + z * hp.x;
        }
        {
            float ar = h0a[2*rs+1] + l0a[2*rs+1]*ILOSC;
            float az = h1a[2*rs+1] + l1a[2*rs+1]*ILOSC;
            float an = h2a[2*rs+1] + l2a[2*rs+1]*ILOSC;
            float r = sigf(gr.y + ar + bhr.y);
            float z = sigf(gz.y + az + bhz.y);
            float n = tanhf(gn.y + r * (an + bhn.y));
            o.y = (1.0f - z) * n + z * hp.y;
        }
        *(float2*)(g_h0n + row * H + jA) = o;
        s_hn[row][jh * 8 + 2 * tc]     = o.x;
        s_hn[row][jh * 8 + 2 * tc + 1] = o.y;
    }
    __syncthreads();
    int b = tid >> 2, tcc = tid & 3;
    int ksb = j0 >> 4;
    g_h0np[(b * 64 + ksb) * 4 + tcc] =
        pack4(s_hn[b][2 * tcc], s_hn[b][2 * tcc + 1],
              s_hn[b][2 * tcc + 8], s_hn[b][2 * tcc + 9]);
}

__device__ __forceinline__ void l1hh_body(int j0, const float* __restrict__ bhh1)
{
    int tid = threadIdx.x, w = tid >> 5, lane = tid & 31;
    int mt = w & 3, jh = w >> 2;
    int g = lane >> 2, tc = lane & 3;
    int b0 = mt * 16 + g;
    int jrow = j0 + jh * 8 + g;

    float h0a[4] = {0,0,0,0}, l0a[4] = {0,0,0,0};
    float h1a[4] = {0,0,0,0}, l1a[4] = {0,0,0,0};
    float h2a[4] = {0,0,0,0}, l2a[4] = {0,0,0,0};
    const uint4* Ap0 = g_h1p + (size_t)b0 * 256 + tc;
    const uint4* Ap1 = Ap0 + 8 * 256;
    const uint4* B0 = g_pW[3] + (size_t)jrow * 256 + tc;
    const uint4* B1 = g_pW[3] + (size_t)(H + jrow) * 256 + tc;
    const uint4* B2 = g_pW[3] + (size_t)(2 * H + jrow) * 256 + tc;

    #pragma unroll 8
    for (int ks = 0; ks < 64; ++ks) {
        uint4 al = __ldcg(Ap0 + ks * 4), ah = __ldcg(Ap1 + ks * 4);
        uint4 w0 = B0[ks * 4], w1 = B1[ks * 4], w2 = B2[ks * 4];
        mma3s(h0a, l0a, al, ah, w0);
        mma3s(h1a, l1a, al, ah, w1);
        mma3s(h2a, l2a, al, ah, w2);
    }
    int jA = j0 + jh * 8 + 2 * tc;
    float2 br = *(const float2*)(bhh1 + jA);
    float2 bz = *(const float2*)(bhh1 + H + jA);
    float2 bn = *(const float2*)(bhh1 + 2 * H + jA);
    #pragma unroll
    for (int rs = 0; rs < 2; ++rs) {
        int row = b0 + 8 * rs;
        float* dst = g_GB + (size_t)row * H3;
        float2 o;
        o.x = h0a[2*rs] + l0a[2*rs]*ILOSC + br.x;
        o.y = h0a[2*rs+1] + l0a[2*rs+1]*ILOSC + br.y; *(float2*)(dst + jA) = o;
        o.x = h1a[2*rs] + l1a[2*rs]*ILOSC + bz.x;
        o.y = h1a[2*rs+1] + l1a[2*rs+1]*ILOSC + bz.y; *(float2*)(dst + H + jA) = o;
        o.x = h2a[2*rs] + l2a[2*rs]*ILOSC + bn.x;
        o.y = h2a[2*rs+1] + l2a[2*rs+1]*ILOSC + bn.y; *(float2*)(dst + 2*H + jA) = o;
    }
}

__device__ __forceinline__ void l1ih_body(int mhalf, int j0,
                                          const float* __restrict__ bih1,
                                          float* s_comb)
{
    int tid = threadIdx.x, w = tid >> 5, lane = tid & 31;
    int mt = w & 1, jh = (w >> 1) & 1, kh = w >> 2;
    int g = lane >> 2, tc = lane & 3;
    int b0 = mhalf * 32 + mt * 16 + g;
    int jrow = j0 + jh * 8 + g;

    float h0a[4] = {0,0,0,0}, l0a[4] = {0,0,0,0};
    float h1a[4] = {0,0,0,0}, l1a[4] = {0,0,0,0};
    float h2a[4] = {0,0,0,0}, l2a[4] = {0,0,0,0};
    const uint4* Ap0 = g_h0np + (size_t)b0 * 256 + tc;
    const uint4* Ap1 = Ap0 + 8 * 256;
    const uint4* B0 = g_pW[2] + (size_t)jrow * 256 + tc;
    const uint4* B1 = g_pW[2] + (size_t)(H + jrow) * 256 + tc;
    const uint4* B2 = g_pW[2] + (size_t)(2 * H + jrow) * 256 + tc;

    int ksb = kh * 32;
    #pragma unroll 4
    for (int ks = ksb; ks < ksb + 32; ++ks) {
        uint4 al = __ldcg(Ap0 + ks * 4), ah = __ldcg(Ap1 + ks * 4);
        uint4 w0 = B0[ks * 4], w1 = B1[ks * 4], w2 = B2[ks * 4];
        mma3s(h0a, l0a, al, ah, w0);
        mma3s(h1a, l1a, al, ah, w1);
        mma3s(h2a, l2a, al, ah, w2);
    }
    float v[12];
    #pragma unroll
    for (int i = 0; i < 4; ++i) {
        v[i]     = h0a[i] + l0a[i] * ILOSC;
        v[4 + i] = h1a[i] + l1a[i] * ILOSC;
        v[8 + i] = h2a[i] + l2a[i] * ILOSC;
    }
    int combo = w & 3;
    float* slot = s_comb + (combo * 32 + lane) * 12;
    if (kh == 1) {
        #pragma unroll
        for (int i = 0; i < 12; ++i) slot[i] = v[i];
    }
    __syncthreads();
    if (kh == 0) {
        #pragma unroll
        for (int i = 0; i < 12; ++i) v[i] += slot[i];
        int jA = j0 + jh * 8 + 2 * tc;
        float2 br = *(const float2*)(bih1 + jA);
        float2 bz = *(const float2*)(bih1 + H + jA);
        float2 bn = *(const float2*)(bih1 + 2 * H + jA);
        #pragma unroll
        for (int rs = 0; rs < 2; ++rs) {
            int row = b0 + 8 * rs;
            float* dst = g_GA + (size_t)row * H3;
            float2 o;
            o.x = v[2*rs]   + br.x; o.y = v[2*rs+1]   + br.y; *(float2*)(dst + jA) = o;
            o.x = v[4+2*rs] + bz.x; o.y = v[4+2*rs+1] + bz.y; *(float2*)(dst + H + jA) = o;
            o.x = v[8+2*rs] + bn.x; o.y = v[8+2*rs+1] + bn.y; *(float2*)(dst + 2*H + jA) = o;
        }
    }
    __syncthreads();
}

__device__ __forceinline__ void update_body(int t, int b,
                                            const int* __restrict__ lengths,
                                            const float* __restrict__ h0,
                                            float* __restrict__ out,
                                            float* s_red, float* s_flags)
{
    int tid = threadIdx.x;
    int ks = tid >> 2, tc = tid & 3;
    int j0a = ks * 16 + 2 * tc;
    const float* A  = g_GA + (size_t)b * H3;
    const float* Bm = g_GB + (size_t)b * H3;

    float h1n[4];
    float dot = 0.0f;
    #pragma unroll
    for (int s2 = 0; s2 < 2; ++s2) {
        int j = j0a + 8 * s2;
        float2 ar  = __ldcg((const float2*)(A + j));
        float2 brv = __ldcg((const float2*)(Bm + j));
        float2 az  = __ldcg((const float2*)(A + H + j));
        float2 bzv = __ldcg((const float2*)(Bm + H + j));
        float2 an  = __ldcg((const float2*)(A + 2 * H + j));
        float2 bnv = __ldcg((const float2*)(Bm + 2 * H + j));
        float2 hp  = __ldcg((const float2*)(g_h1s + b * H + j));
        float2 vv = *(const float2*)(g_v + j);
        {
            float r = sigf(ar.x + brv.x);
            float z = sigf(az.x + bzv.x);
            float n = tanhf(an.x + r * bnv.x);
            float hv = (1.0f - z) * n + z * hp.x;
            h1n[2 * s2] = hv; dot += hv * vv.x;
        }
        {
            float r = sigf(ar.y + brv.y);
            float z = sigf(az.y + bzv.y);
            float n = tanhf(an.y + r * bnv.y);
            float hv = (1.0f - z) * n + z * hp.y;
            h1n[2 * s2 + 1] = hv; dot += hv * vv.y;
        }
    }
    #pragma unroll
    for (int off = 16; off > 0; off >>= 1) dot += __shfl_down_sync(0xffffffffu, dot, off);
    if ((tid & 31) == 0) s_red[tid >> 5] = dot;
    __syncthreads();
    if (tid == 0) {
        float d = 0.0f;
        #pragma unroll
        for (int i = 0; i < 8; ++i) d += s_red[i];
        float a = g_GXF[t * B + b] + d;
        int len = lengths[b];
        float gt = (t == len - 1) ? 1.0f : sigf(a);
        int valid = (t < len);
        out[(size_t)B * T * H + (size_t)b * T + t] = valid ? gt : 0.0f;
        s_flags[0] = valid ? 1.0f : 0.0f;
        s_flags[1] = (valid && gt > 0.5f) ? 1.0f : 0.0f;
    }
    __syncthreads();
    bool valid = s_flags[0] != 0.0f;
    bool reset = s_flags[1] != 0.0f;

    float* orow = out + ((size_t)b * T + t) * H;
    #pragma unroll
    for (int s2 = 0; s2 < 2; ++s2) {
        int j = j0a + 8 * s2;
        float2 o;
        o.x = valid ? h1n[2 * s2] : 0.0f;
        o.y = valid ? h1n[2 * s2 + 1] : 0.0f;
        *(float2*)(orow + j) = o;
    }
    if (valid) {
        float ns0[4], ns1[4];
        #pragma unroll
        for (int s2 = 0; s2 < 2; ++s2) {
            int j = j0a + 8 * s2;
            float2 hi = *(const float2*)(h0 + j);
            float2 c0 = __ldcg((const float2*)(g_h0n + b * H + j));
            float n0x = reset ? hi.x : c0.x;
            float n0y = reset ? hi.y : c0.y;
            float n1x = reset ? hi.x : h1n[2 * s2];
            float n1y = reset ? hi.y : h1n[2 * s2 + 1];
            ns0[2 * s2] = n0x; ns0[2 * s2 + 1] = n0y;
            ns1[2 * s2] = n1x; ns1[2 * s2 + 1] = n1y;
            float2 w0; w0.x = n0x; w0.y = n0y;
            float2 w1; w1.x = n1x; w1.y = n1y;
            *(float2*)(g_h0s + b * H + j) = w0;
            *(float2*)(g_h1s + b * H + j) = w1;
        }
        g_h0p[(b * 64 + ks) * 4 + tc] = pack4(ns0[0], ns0[1], ns0[2], ns0[3]);
        g_h1p[(b * 64 + ks) * 4 + tc] = pack4(ns1[0], ns1[1], ns1[2], ns1[3]);
    }
}

// ---------------- persistent loop kernel ------------------------------------
__global__ void __launch_bounds__(256, 1)
loop_kernel(const int* __restrict__ lengths, const float* __restrict__ h0,
            float* __restrict__ out, const float* __restrict__ bhh0,
            const float* __restrict__ bih1, const float* __restrict__ bhh1)
{
    __shared__ float s_hn[64][17];
    __shared__ float s_comb[4 * 32 * 12];
    __shared__ float s_red[8];
    __shared__ float s_flags[2];
    int blk = blockIdx.x;
    unsigned gen = 0;

    for (int t = 0; t < T; ++t) {
        if (blk < 64) l0_body(t, blk * 16, bhh0, s_hn);
        else          l1hh_body((blk - 64) * 16, bhh1);
        gbar(gen);
        l1ih_body(blk >> 6, (blk & 63) * 16, bih1, s_comb);
        gbar(gen);
        if (blk < 64) update_body(t, blk, lengths, h0, out, s_red, s_flags);
        gbar(gen);
    }
}

// ---------------- host ------------------------------------------------------
extern "C" void kernel_launch(void* const* d_in, const int* in_sizes, int n_in,
                              void* d_out, int out_size)
{
    (void)in_sizes; (void)n_in; (void)out_size;
    const float* x       = (const float*)d_in[0];
    const float* h0      = (const float*)d_in[1];
    const int*   lengths = (const int*)d_in[2];
    const float* W_ih    = (const float*)d_in[3];
    const float* W_hh    = (const float*)d_in[4];
    const float* b_ih    = (const float*)d_in[5];
    const float* b_hh    = (const float*)d_in[6];
    const float* gW1     = (const float*)d_in[7];
    const float* gb1     = (const float*)d_in[8];
    const float* gW2     = (const float*)d_in[9];
    const float* gb2     = (const float*)d_in[10];
    const float* gWF     = (const float*)d_in[11];
    const float* gbF     = (const float*)d_in[12];
    float* out = (float*)d_out;

    const float* bih0 = b_ih;
    const float* bih1 = b_ih + H3;
    const float* bhh0 = b_hh;
    const float* bhh1 = b_hh + H3;

    init_kernel<<<B, 256>>>(h0);
    uvc_kernel<<<33, 64>>>(gW1, gW2, gWF, gb1, gb2, gbF);
    packw_kernel<<<dim3(H3, 4), 256>>>(W_ih, W_hh);
    packx_kernel<<<dim3(T, B), 256>>>(x);
    gxf_kernel<<<dim3(T, B), 128>>>(x);
    gi0_kernel<<<dim3(64, T), 256>>>(bih0);

    loop_kernel<<<NBLK, 256>>>(lengths, h0, out, bhh0, bih1, bhh1);
}

// round 13
// speedup vs baseline: 1.0026x; 1.0026x over previous
#include <cuda_runtime.h>
#include <cuda_fp16.h>
#include <stdint.h>
#include <math.h>

#define H  1024
#define H3 3072
#define B  64
#define T  256
#define LOSC   2048.0f
#define ILOSC  (1.0f/2048.0f)
#define NBLK   128

// ---------------- scratch (static device arrays, no runtime allocation) ----
static __device__ float g_GI0[(size_t)T * B * H3];
static __device__ float g_GXF[T * B];
static __device__ float g_u[H];
static __device__ float g_v[H];
static __device__ float g_c;
static __device__ float g_h0s[B * H];
static __device__ float g_h1s[B * H];
static __device__ float g_h0n[B * H];
static __device__ float g_GA[B * H3];
static __device__ float g_GB[B * H3];

// fragment-packed hi/lo buffers
static __device__ uint4 g_xp[(size_t)B * T * 256];
static __device__ uint4 g_pW[4][(size_t)H3 * 256];
static __device__ uint4 g_h0p [B * 256];
static __device__ uint4 g_h1p [B * 256];
static __device__ uint4 g_h0np[B * 256];

static __device__ unsigned g_barCnt;
static __device__ unsigned g_barGen;

__device__ __forceinline__ float sigf(float x) { return 1.0f / (1.0f + expf(-x)); }

__device__ __forceinline__ unsigned pk2(float a, float b) {
    __half2 h = __floats2half2_rn(a, b);
    return *reinterpret_cast<unsigned*>(&h);
}
__device__ __forceinline__ float rlo(float x) {
    return (x - __half2float(__float2half_rn(x))) * LOSC;
}
__device__ __forceinline__ uint4 pack4(float v0, float v1, float v8, float v9) {
    uint4 p;
    p.x = pk2(v0, v1);           p.y = pk2(v8, v9);
    p.z = pk2(rlo(v0), rlo(v1)); p.w = pk2(rlo(v8), rlo(v9));
    return p;
}

__device__ __forceinline__ void mma_f16(float* c, unsigned a0, unsigned a1,
                                        unsigned a2, unsigned a3,
                                        unsigned b0, unsigned b1) {
    asm volatile(
        "mma.sync.aligned.m16n8k16.row.col.f32.f16.f16.f32 "
        "{%0,%1,%2,%3}, {%4,%5,%6,%7}, {%8,%9}, {%0,%1,%2,%3};\n"
        : "+f"(c[0]), "+f"(c[1]), "+f"(c[2]), "+f"(c[3])
        : "r"(a0), "r"(a1), "r"(a2), "r"(a3), "r"(b0), "r"(b1));
}
__device__ __forceinline__ void mma3s(float* ch, float* cl, const uint4& al,
                                      const uint4& ah, const uint4& wv) {
    mma_f16(ch, al.x, ah.x, al.y, ah.y, wv.x, wv.y);
    mma_f16(cl, al.x, ah.x, al.y, ah.y, wv.z, wv.w);
    mma_f16(cl, al.z, ah.z, al.w, ah.w, wv.x, wv.y);
}

// ---------------- grid barrier (all NBLK blocks co-resident) ----------------
__device__ __forceinline__ void gbar(unsigned& gen) {
    __syncthreads();
    if (threadIdx.x == 0) {
        __threadfence();
        if (atomicAdd(&g_barCnt, 1u) == (unsigned)(NBLK - 1)) {
            g_barCnt = 0u;
            __threadfence();
            atomicExch(&g_barGen, gen + 1u);
        } else {
            while (*((volatile unsigned*)&g_barGen) < gen + 1u) __nanosleep(64);
        }
    }
    __syncthreads();
    ++gen;
}

// ---------------- mega setup kernel (launch 1) -------------------------------
// block ranges: [0,64) init, [64,97) uvc, [97,97+4*H3) packw, then packx.
#define S1_PW_BASE 97
#define S1_PX_BASE (97 + 4 * H3)
#define S1_TOTAL   (S1_PX_BASE + T * B)

__global__ void setup1_kernel(const float* __restrict__ h0,
                              const float* __restrict__ W_ih,
                              const float* __restrict__ W_hh,
                              const float* __restrict__ gW1,
                              const float* __restrict__ gW2,
                              const float* __restrict__ gWF,
                              const float* __restrict__ gb1,
                              const float* __restrict__ gb2,
                              const float* __restrict__ gbF,
                              const float* __restrict__ x)
{
    int bid = blockIdx.x, tid = threadIdx.x;
    if (bid < 64) {
        // init states
        int b = bid;
        int ks = tid >> 2, tc = tid & 3;
        int j = ks * 16 + 2 * tc;
        float2 a = *(const float2*)(h0 + j);
        float2 c = *(const float2*)(h0 + j + 8);
        *(float2*)(g_h0s + b * H + j)     = a;
        *(float2*)(g_h0s + b * H + j + 8) = c;
        *(float2*)(g_h1s + b * H + j)     = a;
        *(float2*)(g_h1s + b * H + j + 8) = c;
        uint4 p = pack4(a.x, a.y, c.x, c.y);
        g_h0p[(b * 64 + ks) * 4 + tc] = p;
        g_h1p[(b * 64 + ks) * 4 + tc] = p;
        if (b == 0 && tid == 0) { g_barCnt = 0u; g_barGen = 0u; }
    } else if (bid < S1_PW_BASE) {
        int u = bid - 64;
        if (u < 32) {
            if (tid < 64) {
                int mat = u >> 4, kc = u & 15;
                const float* W = mat ? gW2 : gW1;
                float* dst = mat ? g_v : g_u;
                int k = kc * 64 + tid;
                float s = 0.0f;
                for (int j = 0; j < H; ++j) s += gWF[j] * W[(size_t)j * H + k];
                dst[k] = s;
            }
        } else {
            __shared__ float red[64];
            if (tid < 64) {
                float s = 0.0f;
                for (int j = tid; j < H; j += 64) s += gWF[j] * (gb1[j] + gb2[j]);
                red[tid] = s;
            }
            __syncthreads();
            if (tid == 0) {
                float d = 0.0f;
                for (int i = 0; i < 64; ++i) d += red[i];
                g_c = d + gbF[0];
            }
        }
    } else if (bid < S1_PX_BASE) {
        // packw: 4 weight matrices into fragment order
        int v = bid - S1_PW_BASE;
        int mat = v / H3;
        int row = v - mat * H3;
        int ks = tid >> 2, tc = tid & 3;
        const float* src = (mat == 0) ? W_ih : (mat == 1) ? W_hh
                         : (mat == 2) ? (W_ih + (size_t)H3 * H) : (W_hh + (size_t)H3 * H);
        int k0 = ks * 16 + 2 * tc;
        const float* r = src + (size_t)row * H;
        float2 a = *(const float2*)(r + k0);
        float2 c = *(const float2*)(r + k0 + 8);
        g_pW[mat][((size_t)row * 64 + ks) * 4 + tc] = pack4(a.x, a.y, c.x, c.y);
    } else {
        // packx
        int v = bid - S1_PX_BASE;
        int t = v & (T - 1);
        int b = v >> 8;
        int ks = tid >> 2, tc = tid & 3;
        int k0 = ks * 16 + 2 * tc;
        const float* r = x + ((size_t)b * T + t) * H;
        float2 a = *(const float2*)(r + k0);
        float2 c = *(const float2*)(r + k0 + 8);
        g_xp[((size_t)(b * T + t) * 64 + ks) * 4 + tc] = pack4(a.x, a.y, c.x, c.y);
    }
}

// ---------------- gate input precompute (launch 2) --------------------------
__global__ void gxf_kernel(const float* __restrict__ x)
{
    int t = blockIdx.x, b = blockIdx.y;
    int tn = (t + 1 < T) ? (t + 1) : (T - 1);
    const float* xr = x + ((size_t)b * T + tn) * H;
    float s = 0.0f;
    for (int k = threadIdx.x; k < H; k += blockDim.x) s += xr[k] * g_u[k];
    __shared__ float red[128];
    red[threadIdx.x] = s;
    __syncthreads();
    for (int off = 64; off > 0; off >>= 1) {
        if (threadIdx.x < off) red[threadIdx.x] += red[threadIdx.x + off];
        __syncthreads();
    }
    if (threadIdx.x == 0) g_GXF[t * B + b] = red[0] + g_c;
}

// ---------------- gi0 (launch 3): retiled mma.sync GEMM ---------------------
// grid (32 j-tiles of 32, 64 t-groups of 4), 256 threads.
// Warp: mt=w&3 (16 m-rows), jh=w>>2 (16-j half). Each warp does TWO 8-j groups.
__global__ void __launch_bounds__(256)
gi0_kernel(const float* __restrict__ bih0)
{
    int tid = threadIdx.x, w = tid >> 5, lane = tid & 31;
    int mt = w & 3, jh = w >> 2;
    int g = lane >> 2, tc = lane & 3;
    int j0n = blockIdx.x * 32 + jh * 16;
    int b0 = mt * 16 + g;
    int jra = j0n + g;

    const uint4* B0a = g_pW[0] + (size_t)jra * 256 + tc;
    const uint4* B1a = g_pW[0] + (size_t)(H + jra) * 256 + tc;
    const uint4* B2a = g_pW[0] + (size_t)(2 * H + jra) * 256 + tc;
    const uint4* B0b = B0a + 8 * 256;
    const uint4* B1b = B1a + 8 * 256;
    const uint4* B2b = B2a + 8 * 256;

    for (int tt = 0; tt < 4; ++tt) {
        int t = blockIdx.y * 4 + tt;
        float h0A[4] = {0,0,0,0}, l0A[4] = {0,0,0,0};
        float h1A[4] = {0,0,0,0}, l1A[4] = {0,0,0,0};
        float h2A[4] = {0,0,0,0}, l2A[4] = {0,0,0,0};
        float h0B[4] = {0,0,0,0}, l0B[4] = {0,0,0,0};
        float h1B[4] = {0,0,0,0}, l1B[4] = {0,0,0,0};
        float h2B[4] = {0,0,0,0}, l2B[4] = {0,0,0,0};
        const uint4* Ap0 = g_xp + ((size_t)b0 * T + t) * 256 + tc;
        const uint4* Ap1 = Ap0 + (size_t)8 * T * 256;

        #pragma unroll 4
        for (int ks = 0; ks < 64; ++ks) {
            uint4 al = Ap0[ks * 4], ah = Ap1[ks * 4];
            uint4 wa0 = B0a[ks * 4], wa1 = B1a[ks * 4], wa2 = B2a[ks * 4];
            uint4 wb0 = B0b[ks * 4], wb1 = B1b[ks * 4], wb2 = B2b[ks * 4];
            mma3s(h0A, l0A, al, ah, wa0);
            mma3s(h1A, l1A, al, ah, wa1);
            mma3s(h2A, l2A, al, ah, wa2);
            mma3s(h0B, l0B, al, ah, wb0);
            mma3s(h1B, l1B, al, ah, wb1);
            mma3s(h2B, l2B, al, ah, wb2);
        }
        int jA = j0n + 2 * tc;
        int jB = jA + 8;
        float2 brA = *(const float2*)(bih0 + jA);
        float2 bzA = *(const float2*)(bih0 + H + jA);
        float2 bnA = *(const float2*)(bih0 + 2 * H + jA);
        float2 brB = *(const float2*)(bih0 + jB);
        float2 bzB = *(const float2*)(bih0 + H + jB);
        float2 bnB = *(const float2*)(bih0 + 2 * H + jB);
        #pragma unroll
        for (int rs = 0; rs < 2; ++rs) {
            int row = b0 + 8 * rs;
            float* dst = g_GI0 + ((size_t)t * B + row) * H3;
            float2 o;
            o.x = h0A[2*rs] + l0A[2*rs]*ILOSC + brA.x;
            o.y = h0A[2*rs+1] + l0A[2*rs+1]*ILOSC + brA.y; *(float2*)(dst + jA) = o;
            o.x = h1A[2*rs] + l1A[2*rs]*ILOSC + bzA.x;
            o.y = h1A[2*rs+1] + l1A[2*rs+1]*ILOSC + bzA.y; *(float2*)(dst + H + jA) = o;
            o.x = h2A[2*rs] + l2A[2*rs]*ILOSC + bnA.x;
            o.y = h2A[2*rs+1] + l2A[2*rs+1]*ILOSC + bnA.y; *(float2*)(dst + 2*H + jA) = o;
            o.x = h0B[2*rs] + l0B[2*rs]*ILOSC + brB.x;
            o.y = h0B[2*rs+1] + l0B[2*rs+1]*ILOSC + brB.y; *(float2*)(dst + jB) = o;
            o.x = h1B[2*rs] + l1B[2*rs]*ILOSC + bzB.x;
            o.y = h1B[2*rs+1] + l1B[2*rs+1]*ILOSC + bzB.y; *(float2*)(dst + H + jB) = o;
            o.x = h2B[2*rs] + l2B[2*rs]*ILOSC + bnB.x;
            o.y = h2B[2*rs+1] + l2B[2*rs+1]*ILOSC + bnB.y; *(float2*)(dst + 2*H + jB) = o;
        }
    }
}

// ---------------- phase bodies (identical to the 8654us kernel) -------------
__device__ __forceinline__ void l0_body(int t, int j0, const float* __restrict__ bhh0,
                                        float (*s_hn)[17])
{
    int tid = threadIdx.x, w = tid >> 5, lane = tid & 31;
    int mt = w & 3, jh = w >> 2;
    int g = lane >> 2, tc = lane & 3;
    int b0 = mt * 16 + g;
    int jrow = j0 + jh * 8 + g;

    float h0a[4] = {0,0,0,0}, l0a[4] = {0,0,0,0};
    float h1a[4] = {0,0,0,0}, l1a[4] = {0,0,0,0};
    float h2a[4] = {0,0,0,0}, l2a[4] = {0,0,0,0};
    const uint4* Ap0 = g_h0p + (size_t)b0 * 256 + tc;
    const uint4* Ap1 = Ap0 + 8 * 256;
    const uint4* B0 = g_pW[1] + (size_t)jrow * 256 + tc;
    const uint4* B1 = g_pW[1] + (size_t)(H + jrow) * 256 + tc;
    const uint4* B2 = g_pW[1] + (size_t)(2 * H + jrow) * 256 + tc;

    #pragma unroll 4
    for (int ks = 0; ks < 64; ++ks) {
        uint4 al = __ldcg(Ap0 + ks * 4), ah = __ldcg(Ap1 + ks * 4);
        uint4 w0 = B0[ks * 4], w1 = B1[ks * 4], w2 = B2[ks * 4];
        mma3s(h0a, l0a, al, ah, w0);
        mma3s(h1a, l1a, al, ah, w1);
        mma3s(h2a, l2a, al, ah, w2);
    }
    int jA = j0 + jh * 8 + 2 * tc;
    float2 bhr = *(const float2*)(bhh0 + jA);
    float2 bhz = *(const float2*)(bhh0 + H + jA);
    float2 bhn = *(const float2*)(bhh0 + 2 * H + jA);
    #pragma unroll
    for (int rs = 0; rs < 2; ++rs) {
        int row = b0 + 8 * rs;
        const float* gi = g_GI0 + ((size_t)t * B + row) * H3;
        float2 gr = *(const float2*)(gi + jA);
        float2 gz = *(const float2*)(gi + H + jA);
        float2 gn = *(const float2*)(gi + 2 * H + jA);
        float2 hp = __ldcg((const float2*)(g_h0s + row * H + jA));
        float2 o;
        {
            float ar = h0a[2*rs] + l0a[2*rs]*ILOSC;
            float az = h1a[2*rs] + l1a[2*rs]*ILOSC;
            float an = h2a[2*rs] + l2a[2*rs]*ILOSC;
            float r = sigf(gr.x + ar + bhr.x);
            float z = sigf(gz.x + az + bhz.x);
            float n = tanhf(gn.x + r * (an + bhn.x));
            o.x = (1.0f - z) * n + z * hp.x;
        }
        {
            float ar = h0a[2*rs+1] + l0a[2*rs+1]*ILOSC;
            float az = h1a[2*rs+1] + l1a[2*rs+1]*ILOSC;
            float an = h2a[2*rs+1] + l2a[2*rs+1]*ILOSC;
            float r = sigf(gr.y + ar + bhr.y);
            float z = sigf(gz.y + az + bhz.y);
            float n = tanhf(gn.y + r * (an + bhn.y));
            o.y = (1.0f - z) * n + z * hp.y;
        }
        *(float2*)(g_h0n + row * H + jA) = o;
        s_hn[row][jh * 8 + 2 * tc]     = o.x;
        s_hn[row][jh * 8 + 2 * tc + 1] = o.y;
    }
    __syncthreads();
    int b = tid >> 2, tcc = tid & 3;
    int ksb = j0 >> 4;
    g_h0np[(b * 64 + ksb) * 4 + tcc] =
        pack4(s_hn[b][2 * tcc], s_hn[b][2 * tcc + 1],
              s_hn[b][2 * tcc + 8], s_hn[b][2 * tcc + 9]);
}

__device__ __forceinline__ void l1hh_body(int j0, const float* __restrict__ bhh1)
{
    int tid = threadIdx.x, w = tid >> 5, lane = tid & 31;
    int mt = w & 3, jh = w >> 2;
    int g = lane >> 2, tc = lane & 3;
    int b0 = mt * 16 + g;
    int jrow = j0 + jh * 8 + g;

    float h0a[4] = {0,0,0,0}, l0a[4] = {0,0,0,0};
    float h1a[4] = {0,0,0,0}, l1a[4] = {0,0,0,0};
    float h2a[4] = {0,0,0,0}, l2a[4] = {0,0,0,0};
    const uint4* Ap0 = g_h1p + (size_t)b0 * 256 + tc;
    const uint4* Ap1 = Ap0 + 8 * 256;
    const uint4* B0 = g_pW[3] + (size_t)jrow * 256 + tc;
    const uint4* B1 = g_pW[3] + (size_t)(H + jrow) * 256 + tc;
    const uint4* B2 = g_pW[3] + (size_t)(2 * H + jrow) * 256 + tc;

    #pragma unroll 4
    for (int ks = 0; ks < 64; ++ks) {
        uint4 al = __ldcg(Ap0 + ks * 4), ah = __ldcg(Ap1 + ks * 4);
        uint4 w0 = B0[ks * 4], w1 = B1[ks * 4], w2 = B2[ks * 4];
        mma3s(h0a, l0a, al, ah, w0);
        mma3s(h1a, l1a, al, ah, w1);
        mma3s(h2a, l2a, al, ah, w2);
    }
    int jA = j0 + jh * 8 + 2 * tc;
    float2 br = *(const float2*)(bhh1 + jA);
    float2 bz = *(const float2*)(bhh1 + H + jA);
    float2 bn = *(const float2*)(bhh1 + 2 * H + jA);
    #pragma unroll
    for (int rs = 0; rs < 2; ++rs) {
        int row = b0 + 8 * rs;
        float* dst = g_GB + (size_t)row * H3;
        float2 o;
        o.x = h0a[2*rs] + l0a[2*rs]*ILOSC + br.x;
        o.y = h0a[2*rs+1] + l0a[2*rs+1]*ILOSC + br.y; *(float2*)(dst + jA) = o;
        o.x = h1a[2*rs] + l1a[2*rs]*ILOSC + bz.x;
        o.y = h1a[2*rs+1] + l1a[2*rs+1]*ILOSC + bz.y; *(float2*)(dst + H + jA) = o;
        o.x = h2a[2*rs] + l2a[2*rs]*ILOSC + bn.x;
        o.y = h2a[2*rs+1] + l2a[2*rs+1]*ILOSC + bn.y; *(float2*)(dst + 2*H + jA) = o;
    }
}

__device__ __forceinline__ void l1ih_body(int mhalf, int j0,
                                          const float* __restrict__ bih1,
                                          float* s_comb)
{
    int tid = threadIdx.x, w = tid >> 5, lane = tid & 31;
    int mt = w & 1, jh = (w >> 1) & 1, kh = w >> 2;
    int g = lane >> 2, tc = lane & 3;
    int b0 = mhalf * 32 + mt * 16 + g;
    int jrow = j0 + jh * 8 + g;

    float h0a[4] = {0,0,0,0}, l0a[4] = {0,0,0,0};
    float h1a[4] = {0,0,0,0}, l1a[4] = {0,0,0,0};
    float h2a[4] = {0,0,0,0}, l2a[4] = {0,0,0,0};
    const uint4* Ap0 = g_h0np + (size_t)b0 * 256 + tc;
    const uint4* Ap1 = Ap0 + 8 * 256;
    const uint4* B0 = g_pW[2] + (size_t)jrow * 256 + tc;
    const uint4* B1 = g_pW[2] + (size_t)(H + jrow) * 256 + tc;
    const uint4* B2 = g_pW[2] + (size_t)(2 * H + jrow) * 256 + tc;

    int ksb = kh * 32;
    #pragma unroll 4
    for (int ks = ksb; ks < ksb + 32; ++ks) {
        uint4 al = __ldcg(Ap0 + ks * 4), ah = __ldcg(Ap1 + ks * 4);
        uint4 w0 = B0[ks * 4], w1 = B1[ks * 4], w2 = B2[ks * 4];
        mma3s(h0a, l0a, al, ah, w0);
        mma3s(h1a, l1a, al, ah, w1);
        mma3s(h2a, l2a, al, ah, w2);
    }
    float v[12];
    #pragma unroll
    for (int i = 0; i < 4; ++i) {
        v[i]     = h0a[i] + l0a[i] * ILOSC;
        v[4 + i] = h1a[i] + l1a[i] * ILOSC;
        v[8 + i] = h2a[i] + l2a[i] * ILOSC;
    }
    int combo = w & 3;
    float* slot = s_comb + (combo * 32 + lane) * 12;
    if (kh == 1) {
        #pragma unroll
        for (int i = 0; i < 12; ++i) slot[i] = v[i];
    }
    __syncthreads();
    if (kh == 0) {
        #pragma unroll
        for (int i = 0; i < 12; ++i) v[i] += slot[i];
        int jA = j0 + jh * 8 + 2 * tc;
        float2 br = *(const float2*)(bih1 + jA);
        float2 bz = *(const float2*)(bih1 + H + jA);
        float2 bn = *(const float2*)(bih1 + 2 * H + jA);
        #pragma unroll
        for (int rs = 0; rs < 2; ++rs) {
            int row = b0 + 8 * rs;
            float* dst = g_GA + (size_t)row * H3;
            float2 o;
            o.x = v[2*rs]   + br.x; o.y = v[2*rs+1]   + br.y; *(float2*)(dst + jA) = o;
            o.x = v[4+2*rs] + bz.x; o.y = v[4+2*rs+1] + bz.y; *(float2*)(dst + H + jA) = o;
            o.x = v[8+2*rs] + bn.x; o.y = v[8+2*rs+1] + bn.y; *(float2*)(dst + 2*H + jA) = o;
        }
    }
    __syncthreads();
}

__device__ __forceinline__ void update_body(int t, int b,
                                            const int* __restrict__ lengths,
                                            const float* __restrict__ h0,
                                            float* __restrict__ out,
                                            float* s_red, float* s_flags)
{
    int tid = threadIdx.x;
    int ks = tid >> 2, tc = tid & 3;
    int j0a = ks * 16 + 2 * tc;
    const float* A  = g_GA + (size_t)b * H3;
    const float* Bm = g_GB + (size_t)b * H3;

    float h1n[4];
    float dot = 0.0f;
    #pragma unroll
    for (int s2 = 0; s2 < 2; ++s2) {
        int j = j0a + 8 * s2;
        float2 ar  = __ldcg((const float2*)(A + j));
        float2 brv = __ldcg((const float2*)(Bm + j));
        float2 az  = __ldcg((const float2*)(A + H + j));
        float2 bzv = __ldcg((const float2*)(Bm + H + j));
        float2 an  = __ldcg((const float2*)(A + 2 * H + j));
        float2 bnv = __ldcg((const float2*)(Bm + 2 * H + j));
        float2 hp  = __ldcg((const float2*)(g_h1s + b * H + j));
        float2 vv = *(const float2*)(g_v + j);
        {
            float r = sigf(ar.x + brv.x);
            float z = sigf(az.x + bzv.x);
            float n = tanhf(an.x + r * bnv.x);
            float hv = (1.0f - z) * n + z * hp.x;
            h1n[2 * s2] = hv; dot += hv * vv.x;
        }
        {
            float r = sigf(ar.y + brv.y);
            float z = sigf(az.y + bzv.y);
            float n = tanhf(an.y + r * bnv.y);
            float hv = (1.0f - z) * n + z * hp.y;
            h1n[2 * s2 + 1] = hv; dot += hv * vv.y;
        }
    }
    #pragma unroll
    for (int off = 16; off > 0; off >>= 1) dot += __shfl_down_sync(0xffffffffu, dot, off);
    if ((tid & 31) == 0) s_red[tid >> 5] = dot;
    __syncthreads();
    if (tid == 0) {
        float d = 0.0f;
        #pragma unroll
        for (int i = 0; i < 8; ++i) d += s_red[i];
        float a = g_GXF[t * B + b] + d;
        int len = lengths[b];
        float gt = (t == len - 1) ? 1.0f : sigf(a);
        int valid = (t < len);
        out[(size_t)B * T * H + (size_t)b * T + t] = valid ? gt : 0.0f;
        s_flags[0] = valid ? 1.0f : 0.0f;
        s_flags[1] = (valid && gt > 0.5f) ? 1.0f : 0.0f;
    }
    __syncthreads();
    bool valid = s_flags[0] != 0.0f;
    bool reset = s_flags[1] != 0.0f;

    float* orow = out + ((size_t)b * T + t) * H;
    #pragma unroll
    for (int s2 = 0; s2 < 2; ++s2) {
        int j = j0a + 8 * s2;
        float2 o;
        o.x = valid ? h1n[2 * s2] : 0.0f;
        o.y = valid ? h1n[2 * s2 + 1] : 0.0f;
        *(float2*)(orow + j) = o;
    }
    if (valid) {
        float ns0[4], ns1[4];
        #pragma unroll
        for (int s2 = 0; s2 < 2; ++s2) {
            int j = j0a + 8 * s2;
            float2 hi = *(const float2*)(h0 + j);
            float2 c0 = __ldcg((const float2*)(g_h0n + b * H + j));
            float n0x = reset ? hi.x : c0.x;
            float n0y = reset ? hi.y : c0.y;
            float n1x = reset ? hi.x : h1n[2 * s2];
            float n1y = reset ? hi.y : h1n[2 * s2 + 1];
            ns0[2 * s2] = n0x; ns0[2 * s2 + 1] = n0y;
            ns1[2 * s2] = n1x; ns1[2 * s2 + 1] = n1y;
            float2 w0; w0.x = n0x; w0.y = n0y;
            float2 w1; w1.x = n1x; w1.y = n1y;
            *(float2*)(g_h0s + b * H + j) = w0;
            *(float2*)(g_h1s + b * H + j) = w1;
        }
        g_h0p[(b * 64 + ks) * 4 + tc] = pack4(ns0[0], ns0[1], ns0[2], ns0[3]);
        g_h1p[(b * 64 + ks) * 4 + tc] = pack4(ns1[0], ns1[1], ns1[2], ns1[3]);
    }
}

// ---------------- persistent loop kernel (launch 4, profiled) ----------------
__global__ void __launch_bounds__(256, 1)
loop_kernel(const int* __restrict__ lengths, const float* __restrict__ h0,
            float* __restrict__ out, const float* __restrict__ bhh0,
            const float* __restrict__ bih1, const float* __restrict__ bhh1)
{
    __shared__ float s_hn[64][17];
    __shared__ float s_comb[4 * 32 * 12];
    __shared__ float s_red[8];
    __shared__ float s_flags[2];
    int blk = blockIdx.x;
    unsigned gen = 0;

    for (int t = 0; t < T; ++t) {
        if (blk < 64) l0_body(t, blk * 16, bhh0, s_hn);
        else          l1hh_body((blk - 64) * 16, bhh1);
        gbar(gen);
        l1ih_body(blk >> 6, (blk & 63) * 16, bih1, s_comb);
        gbar(gen);
        if (blk < 64) update_body(t, blk, lengths, h0, out, s_red, s_flags);
        gbar(gen);
    }
}

// ---------------- host ------------------------------------------------------
extern "C" void kernel_launch(void* const* d_in, const int* in_sizes, int n_in,
                              void* d_out, int out_size)
{
    (void)in_sizes; (void)n_in; (void)out_size;
    const float* x       = (const float*)d_in[0];
    const float* h0      = (const float*)d_in[1];
    const int*   lengths = (const int*)d_in[2];
    const float* W_ih    = (const float*)d_in[3];
    const float* W_hh    = (const float*)d_in[4];
    const float* b_ih    = (const float*)d_in[5];
    const float* b_hh    = (const float*)d_in[6];
    const float* gW1     = (const float*)d_in[7];
    const float* gb1     = (const float*)d_in[8];
    const float* gW2     = (const float*)d_in[9];
    const float* gb2     = (const float*)d_in[10];
    const float* gWF     = (const float*)d_in[11];
    const float* gbF     = (const float*)d_in[12];
    float* out = (float*)d_out;

    const float* bih0 = b_ih;
    const float* bih1 = b_ih + H3;
    const float* bhh0 = b_hh;
    const float* bhh1 = b_hh + H3;

    setup1_kernel<<<S1_TOTAL, 256>>>(h0, W_ih, W_hh, gW1, gW2, gWF, gb1, gb2, gbF, x);
    gxf_kernel<<<dim3(T, B), 128>>>(x);
    gi0_kernel<<<dim3(32, 64), 256>>>(bih0);
    loop_kernel<<<NBLK, 256>>>(lengths, h0, out, bhh0, bih1, bhh1);
}